// round 9
// baseline (speedup 1.0000x reference)
#include <cuda_runtime.h>
#include <cstdint>

// LengthRegulator: out[b, t, :] = x[b, j, :] where token j owns frame t
// (cum[j-1] <= t < cum[j]); zero for t >= cum[L-1]. Second output: durations
// echoed back as float. Shapes: N=16, L=512, D=384, T=3584.
//
// Store path: each block builds a 32-frame (48 KB, GMEM-contiguous) tile in
// SMEM, then ONE cp.async.bulk TMA store drains it at the LTS cap -- removes
// the per-STG.128 LSU issue cost that flooring all previous variants.

#define NB 16
#define LL 512
#define DD 384
#define V4 (DD / 4)                 // 96 float4 per frame
#define GROUPS 4                    // 96-lane groups per block
#define FPT 8                       // frames per thread
#define TILE (GROUPS * FPT)         // 32 frames per block
#define THREADS (V4 * GROUPS)       // 384

// Scratch (allocation-free rule: __device__ globals).
__device__ int g_cum[NB * LL];      // inclusive cumsum of durations
__device__ int g_idx[NB * 4096];    // frame -> token map (T <= 4096)

// ---------------------------------------------------------------------------
// Kernel 1: fused prep. 16 blocks x 512 threads: scan + scatter + echo.
// ---------------------------------------------------------------------------
__global__ void lr_prep_kernel(const int* __restrict__ dur,
                               float* __restrict__ echo_dst) {
    __shared__ int warp_sums[16];
    const int b = blockIdx.x;
    const int j = threadIdx.x;
    const int lane = j & 31;
    const int w = j >> 5;

    const int d = dur[b * LL + j];

    int inc = d;
#pragma unroll
    for (int off = 1; off < 32; off <<= 1) {
        int v = __shfl_up_sync(0xffffffffu, inc, off);
        if (lane >= off) inc += v;
    }
    if (lane == 31) warp_sums[w] = inc;
    __syncthreads();

    if (w == 0) {
        int s = warp_sums[lane & 15];
#pragma unroll
        for (int off = 1; off < 16; off <<= 1) {
            int v = __shfl_up_sync(0xffffffffu, s, off);
            if ((lane & 15) >= off) s += v;
        }
        if (lane < 16) warp_sums[lane] = s;
    }
    __syncthreads();

    const int c = inc + (w > 0 ? warp_sums[w - 1] : 0);
    g_cum[b * LL + j] = c;

    int* row = g_idx + b * 4096;
    const int start = c - d;
    for (int k = 0; k < d; ++k)
        row[start + k] = j;

    if (echo_dst) echo_dst[b * LL + j] = (float)d;
}

// ---------------------------------------------------------------------------
// Kernel 2: expand via SMEM staging + one TMA bulk store per block.
// grid = (T/32, N), block = 384. Thread (g, v) gathers frames t0+8g..t0+8g+7
// (8 independent L2-resident LDG.128), writes them to SMEM, then one elected
// thread bulk-copies the whole 48 KB tile to its contiguous GMEM slot.
// ---------------------------------------------------------------------------
__global__ void __launch_bounds__(THREADS)
lr_expand_kernel(const float* __restrict__ x,
                 float* __restrict__ out, int T) {
    __shared__ float4 sbuf[TILE * V4];        // 48 KB, 16B-aligned
    const int b = blockIdx.y;
    const int tid = threadIdx.x;
    const int g = tid / V4;                   // 0..3
    const int v = tid % V4;                   // 0..95
    const int t0 = blockIdx.x * TILE;
    const int tf = t0 + g * FPT;              // first of this thread's 8 frames

    const int total = __ldg(&g_cum[b * LL + (LL - 1)]);

    // 8 consecutive token ids via two warp-uniform 128-bit loads.
    const int4* jp = reinterpret_cast<const int4*>(&g_idx[b * 4096 + tf]);
    const int4 j0 = jp[0];
    const int4 j1 = jp[1];
    const int js[FPT] = {j0.x, j0.y, j0.z, j0.w, j1.x, j1.y, j1.z, j1.w};

    const float4* xb = reinterpret_cast<const float4*>(x + (size_t)b * LL * DD);

    float4 val[FPT];
#pragma unroll
    for (int k = 0; k < FPT; ++k) {
        val[k] = make_float4(0.f, 0.f, 0.f, 0.f);
        if (tf + k < total)
            val[k] = xb[(size_t)js[k] * V4 + v];      // 8 independent gathers
    }

#pragma unroll
    for (int k = 0; k < FPT; ++k)
        sbuf[(g * FPT + k) * V4 + v] = val[k];        // conflict-free STS.128

    __syncthreads();

    if (tid == 0) {
        asm volatile("fence.proxy.async.shared::cta;" ::: "memory");
        uint32_t saddr;
        asm("{ .reg .u64 t; cvta.to.shared.u64 t, %1; cvt.u32.u64 %0, t; }"
            : "=r"(saddr) : "l"(sbuf));
        const float* dst = out + ((size_t)b * T + t0) * DD;
        asm volatile(
            "cp.async.bulk.global.shared::cta.bulk_group [%0], [%1], %2;"
            :: "l"(dst), "r"(saddr), "r"((int)(TILE * DD * 4)) : "memory");
        asm volatile("cp.async.bulk.commit_group;" ::: "memory");
        asm volatile("cp.async.bulk.wait_group 0;" ::: "memory");
    }
}

extern "C" void kernel_launch(void* const* d_in, const int* in_sizes, int n_in,
                              void* d_out, int out_size) {
    const float* x = (const float*)d_in[0];
    const int* dur = (const int*)d_in[1];

    const int NL = NB * LL;                          // 8192
    const long long per_frame = (long long)NB * DD;  // 6144 elems per time step

    long long main_elems = out_size;
    float* echo_dst = nullptr;
    if (main_elems % per_frame != 0) {
        main_elems -= NL;
        echo_dst = (float*)d_out + main_elems;
    }
    const int T = (int)(main_elems / per_frame);     // 3584

    lr_prep_kernel<<<NB, LL>>>(dur, echo_dst);

    dim3 grid(T / TILE, NB);                         // 112 x 16 = 1792 blocks
    lr_expand_kernel<<<grid, THREADS>>>(x, (float*)d_out, T);
}

// round 10
// speedup vs baseline: 1.0649x; 1.0649x over previous
#include <cuda_runtime.h>

// LengthRegulator, single fused kernel.
// out[b, t, :] = x[b, j, :] where token j owns frame t (cum[j-1] <= t < cum[j]);
// zero for t >= cum[L-1]. Second output: durations echoed as float.
// Shapes: N=16, L=512, D=384, T=3584.
//
// Each block (one 32-frame tile of one batch) redundantly recomputes the
// per-batch scan + frame->token scatter in SMEM (~500 cyc, hidden behind the
// L2-write-bound store stream), then does the 8-frame-ILP gather/store body.

#define NB 16
#define LL 512
#define DD 384
#define V4 (DD / 4)                 // 96 float4 per frame
#define GROUPS 4                    // 96-lane groups per block
#define FPT 8                       // frames per thread
#define TILE (GROUPS * FPT)         // 32 frames per block
#define THREADS (V4 * GROUPS)       // 384
#define TMAX 3584

__global__ void __launch_bounds__(THREADS)
lr_fused_kernel(const float* __restrict__ x,
                const int* __restrict__ dur,
                float* __restrict__ out,
                float* __restrict__ echo_dst, int T) {
    __shared__ int sdur[LL];        // 2 KB
    __shared__ int sidx[TMAX];      // 14 KB frame -> token map
    __shared__ int swsum[4];        // chunk-warp sums
    __shared__ int stotal;

    const int b = blockIdx.y;
    const int tid = threadIdx.x;

    // ---- stage dur row (512 ints with 384 threads) ----
    sdur[tid] = dur[b * LL + tid];
    if (tid < LL - THREADS) sdur[tid + THREADS] = dur[b * LL + tid + THREADS];
    __syncthreads();

    // ---- block scan (threads 0..127, 4 tokens each) + scatter ----
    int a0, a1, a2, a3, s3 = 0, inc = 0;
    if (tid < 128) {
        const int base = tid * 4;
        a0 = sdur[base + 0];
        a1 = sdur[base + 1];
        a2 = sdur[base + 2];
        a3 = sdur[base + 3];
        s3 = a0 + a1 + a2 + a3;

        inc = s3;                                 // inclusive warp scan of chunk sums
        const int lane = tid & 31;
#pragma unroll
        for (int off = 1; off < 32; off <<= 1) {
            int v = __shfl_up_sync(0xffffffffu, inc, off);
            if (lane >= off) inc += v;
        }
        if (lane == 31) swsum[tid >> 5] = inc;
    }
    __syncthreads();

    if (tid < 128) {
        const int w = tid >> 5;
        int wexcl = 0;
#pragma unroll
        for (int k = 0; k < 3; ++k)
            if (k < w) wexcl += swsum[k];

        int c = inc - s3 + wexcl;                 // exclusive prefix before chunk
        const int base = tid * 4;
        const int ds[4] = {a0, a1, a2, a3};
#pragma unroll
        for (int k = 0; k < 4; ++k) {
            const int d = ds[k];
            for (int i = 0; i < d; ++i)
                sidx[c + i] = base + k;
            c += d;
        }
        if (tid == 127) stotal = c;               // total duration of batch
    }

    // ---- echo durations (only the x==0 blocks; 16 total) ----
    if (blockIdx.x == 0 && echo_dst) {
        echo_dst[b * LL + tid] = (float)sdur[tid];
        if (tid < LL - THREADS)
            echo_dst[b * LL + tid + THREADS] = (float)sdur[tid + THREADS];
    }
    __syncthreads();

    // ---- gather/store: 8-frame ILP body (proven R6 structure) ----
    const int g = tid / V4;                       // 0..3
    const int v = tid % V4;                       // 0..95
    const int tf = blockIdx.x * TILE + g * FPT;   // first of this thread's 8 frames
    const int total = stotal;

    // 8 token ids from smem (broadcast across the 96-lane group)
    int js[FPT];
#pragma unroll
    for (int k = 0; k < FPT; ++k)
        js[k] = sidx[tf + k];                     // only used when tf+k < total

    const float4* xb = reinterpret_cast<const float4*>(x + (size_t)b * LL * DD);

    float4 val[FPT];
#pragma unroll
    for (int k = 0; k < FPT; ++k) {
        val[k] = make_float4(0.f, 0.f, 0.f, 0.f);
        if (tf + k < total)
            val[k] = xb[(size_t)js[k] * V4 + v];  // 8 independent gathers
    }

    float4* ob = reinterpret_cast<float4*>(out + ((size_t)b * T + tf) * DD);
#pragma unroll
    for (int k = 0; k < FPT; ++k)
        __stcs(&ob[(size_t)k * V4 + v], val[k]);  // streaming coalesced stores
}

extern "C" void kernel_launch(void* const* d_in, const int* in_sizes, int n_in,
                              void* d_out, int out_size) {
    const float* x = (const float*)d_in[0];
    const int* dur = (const int*)d_in[1];

    const int NL = NB * LL;                          // 8192
    const long long per_frame = (long long)NB * DD;  // 6144 elems per time step

    long long main_elems = out_size;
    float* echo_dst = nullptr;
    if (main_elems % per_frame != 0) {
        main_elems -= NL;
        echo_dst = (float*)d_out + main_elems;
    }
    const int T = (int)(main_elems / per_frame);     // 3584

    dim3 grid(T / TILE, NB);                         // 112 x 16 = 1792 blocks
    lr_fused_kernel<<<grid, THREADS>>>(x, dur, (float*)d_out, echo_dst, T);
}

// round 11
// speedup vs baseline: 1.1369x; 1.0676x over previous
#include <cuda_runtime.h>

// LengthRegulator, single fused kernel with WINDOWED scatter.
// out[b, t, :] = x[b, j, :] where token j owns frame t (cum[j-1] <= t < cum[j]);
// zero for t >= cum[L-1]. Second output: durations echoed as float.
// Shapes: N=16, L=512, D=384, T=3584.
//
// Each block (32 frames of one batch) stages the dur row, scans it in-block,
// then scatters ONLY the 32 token ids covering its own frame window.

#define NB 16
#define LL 512
#define DD 384
#define V4 (DD / 4)                 // 96 float4 per frame
#define GROUPS 4                    // 96-lane groups per block
#define FPT 8                       // frames per thread
#define TILE (GROUPS * FPT)         // 32 frames per block
#define THREADS (V4 * GROUPS)       // 384

__global__ void __launch_bounds__(THREADS)
lr_fused_kernel(const float* __restrict__ x,
                const int* __restrict__ dur,
                float* __restrict__ out,
                float* __restrict__ echo_dst, int T) {
    __shared__ int sdur[LL];        // 2 KB
    __shared__ int sidx[TILE];      // this block's 32 frame->token entries
    __shared__ int swsum[4];        // chunk-warp sums
    __shared__ int stotal;

    const int b = blockIdx.y;
    const int tid = threadIdx.x;
    const int t0 = blockIdx.x * TILE;
    const int t1 = t0 + TILE;

    // ---- stage dur row (512 ints with 384 threads) ----
    sdur[tid] = dur[b * LL + tid];
    if (tid < LL - THREADS) sdur[tid + THREADS] = dur[b * LL + tid + THREADS];
    __syncthreads();

    // ---- block scan over 512 tokens: threads 0..127, 4 tokens each ----
    int a0, a1, a2, a3, s3 = 0, inc = 0;
    if (tid < 128) {
        const int base = tid * 4;
        a0 = sdur[base + 0];
        a1 = sdur[base + 1];
        a2 = sdur[base + 2];
        a3 = sdur[base + 3];
        s3 = a0 + a1 + a2 + a3;

        inc = s3;
        const int lane = tid & 31;
#pragma unroll
        for (int off = 1; off < 32; off <<= 1) {
            int v = __shfl_up_sync(0xffffffffu, inc, off);
            if (lane >= off) inc += v;
        }
        if (lane == 31) swsum[tid >> 5] = inc;
    }
    __syncthreads();

    if (tid < 128) {
        const int w = tid >> 5;
        int wexcl = 0;
#pragma unroll
        for (int k = 0; k < 3; ++k)
            if (k < w) wexcl += swsum[k];

        int c = inc - s3 + wexcl;                 // exclusive prefix before chunk
        const int base = tid * 4;
        const int ds[4] = {a0, a1, a2, a3};
#pragma unroll
        for (int k = 0; k < 4; ++k) {
            const int d = ds[k];
            // windowed scatter: only frames inside [t0, t1)
            const int lo = (c > t0) ? c : t0;
            const int hi = (c + d < t1) ? c + d : t1;
            for (int i = lo; i < hi; ++i)
                sidx[i - t0] = base + k;
            c += d;
        }
        if (tid == 127) stotal = c;               // batch total duration
    }

    // ---- echo durations (only the x==0 blocks; 16 total) ----
    if (blockIdx.x == 0 && echo_dst) {
        echo_dst[b * LL + tid] = (float)sdur[tid];
        if (tid < LL - THREADS)
            echo_dst[b * LL + tid + THREADS] = (float)sdur[tid + THREADS];
    }
    __syncthreads();

    // ---- gather/store: 8-frame ILP body ----
    const int g = tid / V4;                       // 0..3
    const int v = tid % V4;                       // 0..95
    const int tf = t0 + g * FPT;                  // first of this thread's 8 frames
    const int total = stotal;

    int js[FPT];
#pragma unroll
    for (int k = 0; k < FPT; ++k)
        js[k] = sidx[g * FPT + k];                // broadcast across 96-lane group

    const float4* xb = reinterpret_cast<const float4*>(x + (size_t)b * LL * DD);

    float4 val[FPT];
#pragma unroll
    for (int k = 0; k < FPT; ++k) {
        val[k] = make_float4(0.f, 0.f, 0.f, 0.f);
        if (tf + k < total)
            val[k] = xb[(size_t)js[k] * V4 + v];  // 8 independent gathers
    }

    float4* ob = reinterpret_cast<float4*>(out + ((size_t)b * T + tf) * DD);
#pragma unroll
    for (int k = 0; k < FPT; ++k)
        __stcs(&ob[(size_t)k * V4 + v], val[k]);  // streaming coalesced stores
}

extern "C" void kernel_launch(void* const* d_in, const int* in_sizes, int n_in,
                              void* d_out, int out_size) {
    const float* x = (const float*)d_in[0];
    const int* dur = (const int*)d_in[1];

    const int NL = NB * LL;                          // 8192
    const long long per_frame = (long long)NB * DD;  // 6144 elems per time step

    long long main_elems = out_size;
    float* echo_dst = nullptr;
    if (main_elems % per_frame != 0) {
        main_elems -= NL;
        echo_dst = (float*)d_out + main_elems;
    }
    const int T = (int)(main_elems / per_frame);     // 3584

    dim3 grid(T / TILE, NB);                         // 112 x 16 = 1792 blocks
    lr_fused_kernel<<<grid, THREADS>>>(x, dur, (float*)d_out, echo_dst, T);
}